// round 3
// baseline (speedup 1.0000x reference)
#include <cuda_runtime.h>
#include <math.h>

// ---------------- scratch (no allocation allowed) ----------------
#define MAXN 262144
#define SCAN_BLK 1024
#define MAX_NB 512
__device__ int    g_off[MAXN];     // per-element exclusive prefix (local to scan block)
__device__ int    g_bsum[MAX_NB];  // block sums -> exclusive block offsets after k2
__device__ double g_acc[4];        // lp, la, lw, ls sums

// ---------------- kernel 1: local exclusive scan of counts ----------------
__global__ void k_scan_local(const int* __restrict__ counts, int N) {
    __shared__ int sh[SCAN_BLK];
    int gid = blockIdx.x * SCAN_BLK + threadIdx.x;
    int v = (gid < N) ? counts[gid] : 0;
    sh[threadIdx.x] = v;
    __syncthreads();
    // Hillis-Steele inclusive scan
    #pragma unroll
    for (int o = 1; o < SCAN_BLK; o <<= 1) {
        int t = (threadIdx.x >= o) ? sh[threadIdx.x - o] : 0;
        __syncthreads();
        sh[threadIdx.x] += t;
        __syncthreads();
    }
    if (gid < N) g_off[gid] = sh[threadIdx.x] - v;   // exclusive
    if (threadIdx.x == SCAN_BLK - 1) g_bsum[blockIdx.x] = sh[SCAN_BLK - 1];
}

// ---------------- kernel 2: scan block sums (in place -> exclusive), zero acc --
__global__ void k_scan_bsum(int NB) {
    __shared__ int sh[MAX_NB];
    int tid = threadIdx.x;
    int v = (tid < NB) ? g_bsum[tid] : 0;
    sh[tid] = v;
    __syncthreads();
    #pragma unroll
    for (int o = 1; o < MAX_NB; o <<= 1) {
        int t = (tid >= o) ? sh[tid - o] : 0;
        __syncthreads();
        sh[tid] += t;
        __syncthreads();
    }
    if (tid < NB) g_bsum[tid] = sh[tid] - v;        // exclusive
    if (tid < 4)  g_acc[tid] = 0.0;
}

// ---------------- kernel 3: main segmented loss ----------------
__global__ void __launch_bounds__(256) k_main(
    const float* __restrict__ pred,
    const float* __restrict__ gt,
    const int*   __restrict__ counts,
    int N)
{
    const unsigned FULL = 0xffffffffu;
    const int lane   = threadIdx.x & 31;
    const int wInBlk = threadIdx.x >> 5;
    const int warpId = (blockIdx.x * blockDim.x + threadIdx.x) >> 5;
    const int nWarps = (gridDim.x * blockDim.x) >> 5;

    float a0 = 0.f, a1 = 0.f, a2 = 0.f, a3 = 0.f;   // lane-0 accumulators

    for (int s = warpId; s < N; s += nWarps) {
        int cnt = __ldg(counts + s);         // uniform broadcast load
        if (cnt <= 0) continue;
        int off = g_off[s] + g_bsum[s >> 10];

        // pred x,y (uniform across warp)
        float2 pxy = *(const float2*)(pred + (size_t)s * 6);

        float d  = 3.4e38f;
        int   id = 0x7fffffff;
        if (lane < cnt) {
            const float2 g = *(const float2*)(gt + (size_t)(off + lane) * 6);
            float dx = pxy.x - g.x, dy = pxy.y - g.y;
            d  = dx * dx + dy * dy;
            id = off + lane;
        }
        // lexicographic (dist, idx) min reduce — matches reference tie-break
        #pragma unroll
        for (int o = 16; o; o >>= 1) {
            float od = __shfl_down_sync(FULL, d, o);
            int   oi = __shfl_down_sync(FULL, id, o);
            if (od < d || (od == d && oi < id)) { d = od; id = oi; }
        }

        if (lane == 0) {
            // max_resp = exp(-min_dist / (2*sigma^2)); exp monotone decreasing
            a0 += 1.0f - expf(d * (-1.0f / 0.045f));

            const float* ng = gt + (size_t)id * 6;
            float2 g23 = *(const float2*)(ng + 2);
            float2 g45 = *(const float2*)(ng + 4);
            const float* pr = pred + (size_t)s * 6;

            a1 += fabsf(pr[2] - g23.x) + fabsf(pr[3] - g23.y);

            float dd = pr[4] - g45.x;
            float ad = fabsf(dd);
            a2 += (ad < 1.0f) ? 0.5f * dd * dd : ad - 0.5f;

            float x = pr[5], t = g45.y;
            if (t > 0.0f)
                a3 += fmaxf(x, 0.0f) - x * t + log1pf(expf(-fabsf(x)));
        }
    }

    // block reduce (lane 0 of each warp holds partials)
    __shared__ float sh[8][4];
    if (lane == 0) {
        sh[wInBlk][0] = a0; sh[wInBlk][1] = a1;
        sh[wInBlk][2] = a2; sh[wInBlk][3] = a3;
    }
    __syncthreads();
    if (threadIdx.x == 0) {
        float b0 = 0.f, b1 = 0.f, b2 = 0.f, b3 = 0.f;
        int nw = blockDim.x >> 5;
        for (int w = 0; w < nw; w++) {
            b0 += sh[w][0]; b1 += sh[w][1]; b2 += sh[w][2]; b3 += sh[w][3];
        }
        atomicAdd(&g_acc[0], (double)b0);
        atomicAdd(&g_acc[1], (double)b1);
        atomicAdd(&g_acc[2], (double)b2);
        atomicAdd(&g_acc[3], (double)b3);
    }
}

// ---------------- kernel 4: finalize ----------------
__global__ void k_final(float* __restrict__ out, int N) {
    double inv = 1.0 / (double)N;
    double lp = g_acc[0] * inv;
    double la = g_acc[1] * inv;
    double lw = g_acc[2] * inv;
    double ls = g_acc[3] * inv;
    out[0] = (float)lp;
    out[1] = (float)la;
    out[2] = (float)lw;
    out[3] = (float)ls;
    out[4] = (float)(lp + la + lw + 0.5 * ls);   // POS_W=ANG_W=WID_W=1, SCORE_W=0.5
}

extern "C" void kernel_launch(void* const* d_in, const int* in_sizes, int n_in,
                              void* d_out, int out_size) {
    const float* pred   = (const float*)d_in[0];
    const float* gt     = (const float*)d_in[1];
    const int*   counts = (const int*)d_in[2];
    float* out = (float*)d_out;

    int N = in_sizes[2];                 // gt_counts has N elements
    if (N > MAXN) N = MAXN;              // scratch guard (shape contract: N == 262144)
    int NB = (N + SCAN_BLK - 1) / SCAN_BLK;

    k_scan_local<<<NB, SCAN_BLK>>>(counts, N);
    k_scan_bsum<<<1, MAX_NB>>>(NB);
    k_main<<<2048, 256>>>(pred, gt, counts, N);
    k_final<<<1, 1>>>(out, N);
}